// round 1
// baseline (speedup 1.0000x reference)
#include <cuda_runtime.h>
#include <math.h>

#define Bv 32
#define Cv 64
#define NP 192
#define NO 72
#define HDv 64
#define REGD 76
#define ROWS_TOT (Bv*NP)   // 6144

// Transformed (channels-last) feature maps, one per stage
__device__ float d_Ft0[Bv*250*64];    // stage0: x2 (10x25)
__device__ float d_Ft1[Bv*1000*64];   // stage1: x1 (20x50)
__device__ float d_Ft2[Bv*4000*64];   // stage2: x0 (40x100)
__device__ float d_prior[ROWS_TOT*NO];   // prior_xs for next stage
__device__ float d_g[3][ROWS_TOT*Cv];    // per-stage group means

__device__ __forceinline__ float sigmoidf_(float x) {
    return 1.0f / (1.0f + expf(-x));
}

// ---------------------------------------------------------------------------
// kT: Ft[b][hw][c'] = sum_c feat[b][c][hw] * W[c][c']   (transpose + matmul)
// block: 256 threads, 32 pixels. Grid = B*HW/32 (always divides).
// ---------------------------------------------------------------------------
__global__ __launch_bounds__(256, 4)
void kT(const float* __restrict__ feat, const float* __restrict__ Wg,
        int stage, int HW) {
    __shared__ float sin_[32][65];   // padded: avoid 32-way write conflicts
    __shared__ float sW[64*64];
    float* outp = (stage == 0) ? d_Ft0 : (stage == 1 ? d_Ft1 : d_Ft2);

    int tid = threadIdx.x;
    for (int i = tid; i < 4096; i += 256) sW[i] = Wg[i];
    int p0 = blockIdx.x * 32;
    for (int e = tid; e < 2048; e += 256) {
        int c = e >> 5, p = e & 31;
        int gp = p0 + p;
        int b = gp / HW, hw = gp - b * HW;
        sin_[p][c] = feat[(b * 64 + c) * HW + hw];
    }
    __syncthreads();

    int cc = tid & 63, pg = tid >> 6;
    float wcol[64];
#pragma unroll
    for (int c = 0; c < 64; c++) wcol[c] = sW[c * 64 + cc];
#pragma unroll
    for (int pp = 0; pp < 8; pp++) {
        int p = pg * 8 + pp;
        float acc = 0.f;
#pragma unroll
        for (int c = 0; c < 64; c++) acc = fmaf(sin_[p][c], wcol[c], acc);
        outp[(size_t)(p0 + p) * 64 + cc] = acc;
    }
}

// ---------------------------------------------------------------------------
// kS: per (b,n): bilinear-sample 72 points from transformed map (channels-last),
// gate, relu, max over o-pairs, mean over 36 groups -> d_g[stage][row][c]
// block = 128 threads, grid = 6144
// ---------------------------------------------------------------------------
__global__ __launch_bounds__(128, 8)
void kS(int stage, const float* __restrict__ prior0,
        const float* __restrict__ l_weight, int H, int W) {
    const float* Ft = (stage == 0) ? d_Ft0 : (stage == 1 ? d_Ft1 : d_Ft2);
    int row = blockIdx.x;
    int b = row / NP;
    int n = row - b * NP;

    __shared__ int   sidx[72][4];
    __shared__ float swt[72][4];
    __shared__ float sgate[72];
    __shared__ float v[72][64];
    __shared__ float red[128];

    int tid = threadIdx.x;
    if (tid < 72) {
        int o = tid;
        float px = (stage == 0) ? prior0[n * NO + o] : d_prior[row * NO + o];
        float gx = px * 2.0f - 1.0f;
        float ix = (gx + 1.0f) * 0.5f * (float)(W - 1);
        float yo = 1.0f - (float)o * (1.0f / 71.0f);
        float gy = yo * 2.0f - 1.0f;
        float iy = (gy + 1.0f) * 0.5f * (float)(H - 1);
        float ix0f = floorf(ix), iy0f = floorf(iy);
        float wx = ix - ix0f, wy = iy - iy0f;
        int ix0 = min(max((int)ix0f, 0), W - 1);
        int iy0 = min(max((int)iy0f, 0), H - 1);
        int ix1 = min(ix0 + 1, W - 1);
        int iy1 = min(iy0 + 1, H - 1);
        sidx[o][0] = (iy0 * W + ix0) * 64;
        sidx[o][1] = (iy0 * W + ix1) * 64;
        sidx[o][2] = (iy1 * W + ix0) * 64;
        sidx[o][3] = (iy1 * W + ix1) * 64;
        swt[o][0] = (1.f - wx) * (1.f - wy);
        swt[o][1] = wx * (1.f - wy);
        swt[o][2] = (1.f - wx) * wy;
        swt[o][3] = wx * wy;
        sgate[o] = sigmoidf_(l_weight[o]);
    }
    __syncthreads();

    const float* base = Ft + (size_t)b * ((size_t)H * W * 64);
    int c4 = tid & 15, osub = tid >> 4;   // 16 float4-lanes x 8 o's per iter
#pragma unroll
    for (int it = 0; it < 9; it++) {
        int o = it * 8 + osub;
        float4 a0 = *((const float4*)(base + sidx[o][0]) + c4);
        float4 a1 = *((const float4*)(base + sidx[o][1]) + c4);
        float4 a2 = *((const float4*)(base + sidx[o][2]) + c4);
        float4 a3 = *((const float4*)(base + sidx[o][3]) + c4);
        float w0 = swt[o][0], w1 = swt[o][1], w2 = swt[o][2], w3 = swt[o][3];
        float g = sgate[o];
        float4 r;
        r.x = fmaxf(0.f, g * (w0 * a0.x + w1 * a1.x + w2 * a2.x + w3 * a3.x));
        r.y = fmaxf(0.f, g * (w0 * a0.y + w1 * a1.y + w2 * a2.y + w3 * a3.y));
        r.z = fmaxf(0.f, g * (w0 * a0.z + w1 * a1.z + w2 * a2.z + w3 * a3.z));
        r.w = fmaxf(0.f, g * (w0 * a0.w + w1 * a1.w + w2 * a2.w + w3 * a3.w));
        ((float4*)&v[o][0])[c4] = r;
    }
    __syncthreads();

    int c = tid & 63, hh = tid >> 6;
    float acc = 0.f;
#pragma unroll
    for (int gI = 0; gI < 18; gI++) {
        int o = (hh * 18 + gI) * 2;
        acc += fmaxf(v[o][c], v[o + 1][c]);
    }
    red[tid] = acc;
    __syncthreads();
    if (tid < 64)
        d_g[stage][(size_t)row * 64 + c] = (red[tid] + red[tid + 64]) * (1.0f / 36.0f);
}

// ---------------------------------------------------------------------------
// kH: heads. 256 threads = 4 rows x 64 units. grid = 1536.
// fused = mean over stages<=s of d_g, then fc + 3 MLP heads; writes outs[s]
// and d_prior = sigmoid(reg[4:]).
// ---------------------------------------------------------------------------
__global__ __launch_bounds__(256, 4)
void kH(int s,
        const float* __restrict__ fc_w,  const float* __restrict__ fc_b,
        const float* __restrict__ cls_w, const float* __restrict__ cls_b,
        const float* __restrict__ cls_ow,const float* __restrict__ cls_ob,
        const float* __restrict__ reg_w, const float* __restrict__ reg_b,
        const float* __restrict__ reg_ow,const float* __restrict__ reg_ob,
        const float* __restrict__ loc_w, const float* __restrict__ loc_b,
        const float* __restrict__ loc_ow,const float* __restrict__ loc_ob,
        float* __restrict__ out) {
    int lr = threadIdx.x >> 6, t = threadIdx.x & 63;
    int row = blockIdx.x * 4 + lr;
    __shared__ float A[4][64], Bf[4][64], Cc[4][64], D[4][64];

    float fv = d_g[0][(size_t)row * 64 + t];
    if (s >= 1) fv += d_g[1][(size_t)row * 64 + t];
    if (s >= 2) fv += d_g[2][(size_t)row * 64 + t];
    A[lr][t] = fv * (1.0f / (float)(s + 1));
    __syncthreads();

    // fc
    float acc = fc_b[t];
#pragma unroll
    for (int i = 0; i < 64; i++) acc = fmaf(A[lr][i], fc_w[i * 64 + t], acc);
    Bf[lr][t] = fmaxf(acc, 0.f);
    __syncthreads();

    float* orow = out + ((size_t)s * ROWS_TOT + row) * 79;

    // ---- cls head ----
    acc = cls_b[t];
#pragma unroll
    for (int i = 0; i < 64; i++) acc = fmaf(Bf[lr][i], cls_w[i * 64 + t], acc);
    Cc[lr][t] = fmaxf(acc, 0.f);
    __syncthreads();
    acc = cls_b[64 + t];
#pragma unroll
    for (int i = 0; i < 64; i++) acc = fmaf(Cc[lr][i], cls_w[4096 + i * 64 + t], acc);
    D[lr][t] = fmaxf(acc, 0.f);
    __syncthreads();
    if (t < 2) {
        float o = cls_ob[t];
#pragma unroll
        for (int i = 0; i < 64; i++) o = fmaf(D[lr][i], cls_ow[i * 2 + t], o);
        orow[t] = o;
    }
    __syncthreads();

    // ---- reg head ----
    acc = reg_b[t];
#pragma unroll
    for (int i = 0; i < 64; i++) acc = fmaf(Bf[lr][i], reg_w[i * 64 + t], acc);
    Cc[lr][t] = fmaxf(acc, 0.f);
    __syncthreads();
    acc = reg_b[64 + t];
#pragma unroll
    for (int i = 0; i < 64; i++) acc = fmaf(Cc[lr][i], reg_w[4096 + i * 64 + t], acc);
    D[lr][t] = fmaxf(acc, 0.f);
    __syncthreads();
    {
        float r0 = reg_ob[t];
#pragma unroll
        for (int i = 0; i < 64; i++) r0 = fmaf(D[lr][i], reg_ow[i * REGD + t], r0);
        orow[2 + t] = r0;
        if (t >= 4) d_prior[(size_t)row * NO + (t - 4)] = sigmoidf_(r0);
        if (t < 12) {
            int k = t + 64;
            float r1 = reg_ob[k];
#pragma unroll
            for (int i = 0; i < 64; i++) r1 = fmaf(D[lr][i], reg_ow[i * REGD + k], r1);
            orow[2 + k] = r1;
            d_prior[(size_t)row * NO + (k - 4)] = sigmoidf_(r1);
        }
    }
    __syncthreads();

    // ---- loc head ----
    acc = loc_b[t];
#pragma unroll
    for (int i = 0; i < 64; i++) acc = fmaf(Bf[lr][i], loc_w[i * 64 + t], acc);
    Cc[lr][t] = fmaxf(acc, 0.f);
    __syncthreads();
    acc = loc_b[64 + t];
#pragma unroll
    for (int i = 0; i < 64; i++) acc = fmaf(Cc[lr][i], loc_w[4096 + i * 64 + t], acc);
    D[lr][t] = fmaxf(acc, 0.f);
    __syncthreads();
    if (t == 0) {
        float o = loc_ob[0];
#pragma unroll
        for (int i = 0; i < 64; i++) o = fmaf(D[lr][i], loc_ow[i], o);
        orow[78] = o;
    }
}

// ---------------------------------------------------------------------------
extern "C" void kernel_launch(void* const* d_in, const int* in_sizes, int n_in,
                              void* d_out, int out_size) {
    const float* x0       = (const float*)d_in[0];
    const float* x1       = (const float*)d_in[1];
    const float* x2       = (const float*)d_in[2];
    const float* prior0   = (const float*)d_in[3];
    const float* l_weight = (const float*)d_in[4];
    const float* lsgi_w   = (const float*)d_in[5];
    const float* fc_w     = (const float*)d_in[6];
    const float* fc_b     = (const float*)d_in[7];
    const float* cls_w    = (const float*)d_in[8];
    const float* cls_b    = (const float*)d_in[9];
    const float* cls_ow   = (const float*)d_in[10];
    const float* cls_ob   = (const float*)d_in[11];
    const float* reg_w    = (const float*)d_in[12];
    const float* reg_b    = (const float*)d_in[13];
    const float* reg_ow   = (const float*)d_in[14];
    const float* reg_ob   = (const float*)d_in[15];
    const float* loc_w    = (const float*)d_in[16];
    const float* loc_b    = (const float*)d_in[17];
    const float* loc_ow   = (const float*)d_in[18];
    const float* loc_ob   = (const float*)d_in[19];
    float* out = (float*)d_out;

    // Precompute transformed channels-last maps (stage s uses pyramid[s] = x2,x1,x0)
    kT<<<250,  256>>>(x2, lsgi_w + 0 * 4096, 0, 250);
    kT<<<1000, 256>>>(x1, lsgi_w + 1 * 4096, 1, 1000);
    kT<<<4000, 256>>>(x0, lsgi_w + 2 * 4096, 2, 4000);

    const int Hs[3] = {10, 20, 40};
    const int Ws[3] = {25, 50, 100};
    for (int s = 0; s < 3; s++) {
        kS<<<ROWS_TOT, 128>>>(s, prior0, l_weight, Hs[s], Ws[s]);
        kH<<<ROWS_TOT / 4, 256>>>(s,
            fc_w, fc_b, cls_w, cls_b, cls_ow, cls_ob,
            reg_w, reg_b, reg_ow, reg_ob, loc_w, loc_b, loc_ow, loc_ob,
            out);
    }
}

// round 3
// speedup vs baseline: 1.1137x; 1.1137x over previous
#include <cuda_runtime.h>
#include <math.h>

#define ROWS 6144            // B*Np = 32*192

// Transformed channels-last feature maps
__device__ float d_Ft0[32*250*64];     // stage0: x2 (10x25)
__device__ float d_Ft1[32*1000*64];    // stage1: x1 (20x50)
__device__ float d_Ft2[32*4000*64];    // stage2: x0 (40x100)
__device__ float d_prior[ROWS*72];
__device__ float d_g[3][ROWS*64];

__device__ __forceinline__ float sigm(float x) { return 1.0f / (1.0f + expf(-x)); }

// ===========================================================================
// kT body: transpose+matmul. 64 pixels x 64 out-channels per block, 256 thr.
// Thread tile: 4 px x 4 cc (float4). No register spills.
// ===========================================================================
struct SmemT {
    float sin_[64][65];   // [px][c], padded
    float sW[64*64];      // [c][cc]
};

__device__ __forceinline__ void kT_body(
    SmemT* sm, const float* __restrict__ feat, const float* __restrict__ Wg,
    float* __restrict__ outp, int p0, int HW)
{
    int tid = threadIdx.x;
    for (int i = tid; i < 4096; i += 256) sm->sW[i] = Wg[i];
    for (int e = tid; e < 4096; e += 256) {
        int c = e >> 6, p = e & 63;
        int gp = p0 + p;
        int b = gp / HW, hw = gp - b * HW;
        sm->sin_[p][c] = feat[(size_t)(b * 64 + c) * HW + hw];
    }
    __syncthreads();

    int cgrp = tid & 15, pgrp = tid >> 4;
    float acc[4][4];
#pragma unroll
    for (int i = 0; i < 4; i++)
#pragma unroll
        for (int j = 0; j < 4; j++) acc[i][j] = 0.f;

#pragma unroll 8
    for (int c = 0; c < 64; c++) {
        float4 w4 = *(const float4*)&sm->sW[c * 64 + cgrp * 4];
#pragma unroll
        for (int pp = 0; pp < 4; pp++) {
            float sv = sm->sin_[pgrp * 4 + pp][c];
            acc[pp][0] = fmaf(sv, w4.x, acc[pp][0]);
            acc[pp][1] = fmaf(sv, w4.y, acc[pp][1]);
            acc[pp][2] = fmaf(sv, w4.z, acc[pp][2]);
            acc[pp][3] = fmaf(sv, w4.w, acc[pp][3]);
        }
    }
#pragma unroll
    for (int pp = 0; pp < 4; pp++) {
        float4 r = make_float4(acc[pp][0], acc[pp][1], acc[pp][2], acc[pp][3]);
        *(float4*)&outp[(size_t)(p0 + pgrp * 4 + pp) * 64 + cgrp * 4] = r;
    }
}

// ===========================================================================
// kSH body: sample+pool+heads for 2 rows per block (256 threads).
// htid = tid&127 works one row; pair-max done via shfl_xor(16).
// ===========================================================================
struct SmemSH {
    int   sidx[2][72][4];
    float swt[2][72][4];
    float sgate[72];
    float sacc[2][4][64];
    float A[2][64], Bf[2][64];
    float C1[2][2][64], D1[2][2][64];   // [half][grp(cls/reg)][unit]
    float Cloc[2][64], Dloc[2][64];
};

__device__ __forceinline__ void kSH_body(
    SmemSH* sm, int stage, int row0, int H, int W,
    const float* __restrict__ prior0, const float* __restrict__ l_weight,
    const float* __restrict__ fc_w,  const float* __restrict__ fc_b,
    const float* __restrict__ cls_w, const float* __restrict__ cls_b,
    const float* __restrict__ cls_ow,const float* __restrict__ cls_ob,
    const float* __restrict__ reg_w, const float* __restrict__ reg_b,
    const float* __restrict__ reg_ow,const float* __restrict__ reg_ob,
    const float* __restrict__ loc_w, const float* __restrict__ loc_b,
    const float* __restrict__ loc_ow,const float* __restrict__ loc_ob,
    float* __restrict__ out)
{
    int tid = threadIdx.x;
    int htid = tid & 127, half = tid >> 7;
    int row = row0 + half;
    int b = row / 192, n = row - b * 192;

    if (tid < 72) sm->sgate[tid] = sigm(l_weight[tid]);
    if (htid < 72) {
        int o = htid;
        float px = (stage == 0) ? prior0[n * 72 + o] : d_prior[row * 72 + o];
        float gx = px * 2.0f - 1.0f;
        float ix = (gx + 1.0f) * 0.5f * (float)(W - 1);
        float yo = 1.0f - (float)o * (1.0f / 71.0f);
        float gy = yo * 2.0f - 1.0f;
        float iy = (gy + 1.0f) * 0.5f * (float)(H - 1);
        float ix0f = floorf(ix), iy0f = floorf(iy);
        float wx = ix - ix0f, wy = iy - iy0f;
        int ix0 = min(max((int)ix0f, 0), W - 1);
        int iy0 = min(max((int)iy0f, 0), H - 1);
        int ix1 = min(ix0 + 1, W - 1);
        int iy1 = min(iy0 + 1, H - 1);
        sm->sidx[half][o][0] = (iy0 * W + ix0) * 64;
        sm->sidx[half][o][1] = (iy0 * W + ix1) * 64;
        sm->sidx[half][o][2] = (iy1 * W + ix0) * 64;
        sm->sidx[half][o][3] = (iy1 * W + ix1) * 64;
        sm->swt[half][o][0] = (1.f - wx) * (1.f - wy);
        sm->swt[half][o][1] = wx * (1.f - wy);
        sm->swt[half][o][2] = (1.f - wx) * wy;
        sm->swt[half][o][3] = wx * wy;
    }
    __syncthreads();

    const float* Ft = (stage == 0) ? d_Ft0 : (stage == 1 ? d_Ft1 : d_Ft2);
    const float* base = Ft + (size_t)b * ((size_t)H * W * 64);
    int c4 = htid & 15, osub = htid >> 4;   // osub in [0,8)

    float4 acc = make_float4(0.f, 0.f, 0.f, 0.f);
#pragma unroll
    for (int it = 0; it < 9; it++) {
        int o = it * 8 + osub;
        const int* si = sm->sidx[half][o];
        float4 a0 = *((const float4*)(base + si[0]) + c4);
        float4 a1 = *((const float4*)(base + si[1]) + c4);
        float4 a2 = *((const float4*)(base + si[2]) + c4);
        float4 a3 = *((const float4*)(base + si[3]) + c4);
        float w0 = sm->swt[half][o][0], w1 = sm->swt[half][o][1];
        float w2 = sm->swt[half][o][2], w3 = sm->swt[half][o][3];
        float g = sm->sgate[o];
        float4 r;
        r.x = fmaxf(0.f, g * (w0 * a0.x + w1 * a1.x + w2 * a2.x + w3 * a3.x));
        r.y = fmaxf(0.f, g * (w0 * a0.y + w1 * a1.y + w2 * a2.y + w3 * a3.y));
        r.z = fmaxf(0.f, g * (w0 * a0.z + w1 * a1.z + w2 * a2.z + w3 * a3.z));
        r.w = fmaxf(0.f, g * (w0 * a0.w + w1 * a1.w + w2 * a2.w + w3 * a3.w));
        // neighbor osub (odd) is 16 lanes away in the same warp
        float qx = __shfl_xor_sync(0xffffffffu, r.x, 16);
        float qy = __shfl_xor_sync(0xffffffffu, r.y, 16);
        float qz = __shfl_xor_sync(0xffffffffu, r.z, 16);
        float qw = __shfl_xor_sync(0xffffffffu, r.w, 16);
        if ((osub & 1) == 0) {
            acc.x += fmaxf(r.x, qx);
            acc.y += fmaxf(r.y, qy);
            acc.z += fmaxf(r.z, qz);
            acc.w += fmaxf(r.w, qw);
        }
    }
    if ((osub & 1) == 0) {
        int w = (htid >> 5) & 3;
        *(float4*)&sm->sacc[half][w][c4 * 4] = acc;
    }
    __syncthreads();

    int grp = htid >> 6, u = htid & 63;

    if (grp == 0) {
        float fv = sm->sacc[half][0][u] + sm->sacc[half][1][u] +
                   sm->sacc[half][2][u] + sm->sacc[half][3][u];
        fv *= (1.0f / 36.0f);
        d_g[stage][(size_t)row * 64 + u] = fv;
        if (stage >= 1) fv += d_g[0][(size_t)row * 64 + u];
        if (stage == 2) fv += d_g[1][(size_t)row * 64 + u];
        sm->A[half][u] = fv * (1.0f / (float)(stage + 1));
    }
    __syncthreads();

    if (grp == 0) {   // fc
        float a = fc_b[u];
#pragma unroll
        for (int i = 0; i < 64; i++) a = fmaf(sm->A[half][i], fc_w[i * 64 + u], a);
        sm->Bf[half][u] = fmaxf(a, 0.f);
    }
    __syncthreads();

    // layer 1: grp0 -> cls, grp1 -> reg
    {
        const float* w = (grp == 0) ? cls_w : reg_w;
        const float* bb = (grp == 0) ? cls_b : reg_b;
        float a = bb[u];
#pragma unroll
        for (int i = 0; i < 64; i++) a = fmaf(sm->Bf[half][i], w[i * 64 + u], a);
        sm->C1[half][grp][u] = fmaxf(a, 0.f);
    }
    __syncthreads();
    {
        const float* w = (grp == 0) ? cls_w : reg_w;
        const float* bb = (grp == 0) ? cls_b : reg_b;
        float a = bb[64 + u];
#pragma unroll
        for (int i = 0; i < 64; i++) a = fmaf(sm->C1[half][grp][i], w[4096 + i * 64 + u], a);
        sm->D1[half][grp][u] = fmaxf(a, 0.f);
    }
    __syncthreads();

    float* orow = out + ((size_t)stage * ROWS + row) * 79;
    if (grp == 0) {
        if (u < 2) {
            float o = cls_ob[u];
#pragma unroll
            for (int i = 0; i < 64; i++) o = fmaf(sm->D1[half][0][i], cls_ow[i * 2 + u], o);
            orow[u] = o;
        }
        // loc layer 1 (reads Bf)
        float a = loc_b[u];
#pragma unroll
        for (int i = 0; i < 64; i++) a = fmaf(sm->Bf[half][i], loc_w[i * 64 + u], a);
        sm->Cloc[half][u] = fmaxf(a, 0.f);
    } else {
        float r0 = reg_ob[u];
#pragma unroll
        for (int i = 0; i < 64; i++) r0 = fmaf(sm->D1[half][1][i], reg_ow[i * 76 + u], r0);
        orow[2 + u] = r0;
        if (u >= 4) d_prior[(size_t)row * 72 + (u - 4)] = sigm(r0);
        if (u < 12) {
            int k = u + 64;
            float r1 = reg_ob[k];
#pragma unroll
            for (int i = 0; i < 64; i++) r1 = fmaf(sm->D1[half][1][i], reg_ow[i * 76 + k], r1);
            orow[2 + k] = r1;
            d_prior[(size_t)row * 72 + (k - 4)] = sigm(r1);
        }
    }
    __syncthreads();
    if (grp == 0) {   // loc layer 2
        float a = loc_b[64 + u];
#pragma unroll
        for (int i = 0; i < 64; i++) a = fmaf(sm->Cloc[half][i], loc_w[4096 + i * 64 + u], a);
        sm->Dloc[half][u] = fmaxf(a, 0.f);
    }
    __syncthreads();
    if (grp == 0 && u == 0) {
        float o = loc_ob[0];
#pragma unroll
        for (int i = 0; i < 64; i++) o = fmaf(sm->Dloc[half][i], loc_ow[i], o);
        orow[78] = o;
    }
}

// ===========================================================================
// Kernels
// ===========================================================================
__global__ __launch_bounds__(256)
void kT0(const float* __restrict__ x2, const float* __restrict__ lsgi_w) {
    __shared__ SmemT sm;
    kT_body(&sm, x2, lsgi_w, d_Ft0, blockIdx.x * 64, 250);
}

// Mixed launch: interleaved kSH(stage0) blocks (3072) + kT(stage1/2) blocks (2500)
__global__ __launch_bounds__(256)
void kMix(const float* __restrict__ x0, const float* __restrict__ x1,
          const float* __restrict__ lsgi_w,
          const float* __restrict__ prior0, const float* __restrict__ l_weight,
          const float* __restrict__ fc_w,  const float* __restrict__ fc_b,
          const float* __restrict__ cls_w, const float* __restrict__ cls_b,
          const float* __restrict__ cls_ow,const float* __restrict__ cls_ob,
          const float* __restrict__ reg_w, const float* __restrict__ reg_b,
          const float* __restrict__ reg_ow,const float* __restrict__ reg_ob,
          const float* __restrict__ loc_w, const float* __restrict__ loc_b,
          const float* __restrict__ loc_ow,const float* __restrict__ loc_ob,
          float* __restrict__ out)
{
    __shared__ union USm { SmemT t; SmemSH s; } sm;
    int bx = blockIdx.x;
    bool isT; int idx;
    if (bx < 5000) { isT = ((bx & 1) == 0); idx = bx >> 1; }
    else           { isT = false; idx = 2500 + (bx - 5000); }

    if (isT) {
        if (idx < 500) kT_body(&sm.t, x1, lsgi_w + 4096, d_Ft1, idx * 64, 1000);
        else           kT_body(&sm.t, x0, lsgi_w + 8192, d_Ft2, (idx - 500) * 64, 4000);
    } else {
        kSH_body(&sm.s, 0, idx * 2, 10, 25, prior0, l_weight,
                 fc_w, fc_b, cls_w, cls_b, cls_ow, cls_ob,
                 reg_w, reg_b, reg_ow, reg_ob, loc_w, loc_b, loc_ow, loc_ob, out);
    }
}

__global__ __launch_bounds__(256, 6)
void kSHk(int stage, int H, int W,
          const float* __restrict__ prior0, const float* __restrict__ l_weight,
          const float* __restrict__ fc_w,  const float* __restrict__ fc_b,
          const float* __restrict__ cls_w, const float* __restrict__ cls_b,
          const float* __restrict__ cls_ow,const float* __restrict__ cls_ob,
          const float* __restrict__ reg_w, const float* __restrict__ reg_b,
          const float* __restrict__ reg_ow,const float* __restrict__ reg_ob,
          const float* __restrict__ loc_w, const float* __restrict__ loc_b,
          const float* __restrict__ loc_ow,const float* __restrict__ loc_ob,
          float* __restrict__ out)
{
    __shared__ SmemSH sm;
    kSH_body(&sm, stage, blockIdx.x * 2, H, W, prior0, l_weight,
             fc_w, fc_b, cls_w, cls_b, cls_ow, cls_ob,
             reg_w, reg_b, reg_ow, reg_ob, loc_w, loc_b, loc_ow, loc_ob, out);
}

// ===========================================================================
extern "C" void kernel_launch(void* const* d_in, const int* in_sizes, int n_in,
                              void* d_out, int out_size) {
    const float* x0       = (const float*)d_in[0];
    const float* x1       = (const float*)d_in[1];
    const float* x2       = (const float*)d_in[2];
    const float* prior0   = (const float*)d_in[3];
    const float* l_weight = (const float*)d_in[4];
    const float* lsgi_w   = (const float*)d_in[5];
    const float* fc_w     = (const float*)d_in[6];
    const float* fc_b     = (const float*)d_in[7];
    const float* cls_w    = (const float*)d_in[8];
    const float* cls_b    = (const float*)d_in[9];
    const float* cls_ow   = (const float*)d_in[10];
    const float* cls_ob   = (const float*)d_in[11];
    const float* reg_w    = (const float*)d_in[12];
    const float* reg_b    = (const float*)d_in[13];
    const float* reg_ow   = (const float*)d_in[14];
    const float* reg_ob   = (const float*)d_in[15];
    const float* loc_w    = (const float*)d_in[16];
    const float* loc_b    = (const float*)d_in[17];
    const float* loc_ow   = (const float*)d_in[18];
    const float* loc_ob   = (const float*)d_in[19];
    float* out = (float*)d_out;

    kT0<<<125, 256>>>(x2, lsgi_w);

    kMix<<<5572, 256>>>(x0, x1, lsgi_w, prior0, l_weight,
                        fc_w, fc_b, cls_w, cls_b, cls_ow, cls_ob,
                        reg_w, reg_b, reg_ow, reg_ob,
                        loc_w, loc_b, loc_ow, loc_ob, out);

    kSHk<<<3072, 256>>>(1, 20, 50, prior0, l_weight,
                        fc_w, fc_b, cls_w, cls_b, cls_ow, cls_ob,
                        reg_w, reg_b, reg_ow, reg_ob,
                        loc_w, loc_b, loc_ow, loc_ob, out);

    kSHk<<<3072, 256>>>(2, 40, 100, prior0, l_weight,
                        fc_w, fc_b, cls_w, cls_b, cls_ow, cls_ob,
                        reg_w, reg_b, reg_ow, reg_ob,
                        loc_w, loc_b, loc_ow, loc_ob, out);
}

// round 7
// speedup vs baseline: 1.3808x; 1.2399x over previous
#include <cuda_runtime.h>
#include <math.h>

#define ROWS 6144            // B*Np = 32*192

__device__ float d_Ft0[32*250*64];     // stage0: x2 (10x25)
__device__ float d_Ft1[32*1000*64];    // stage1: x1 (20x50)
__device__ float d_Ft2[32*4000*64];    // stage2: x0 (40x100)
__device__ float d_prior[ROWS*72];
__device__ float d_g[3][ROWS*64];

__device__ __forceinline__ float sigm(float x) { return 1.0f / (1.0f + expf(-x)); }

// ===========================================================================
// kT body: transpose+matmul. 64 pixels x 64 out-channels per block, 256 thr.
// ===========================================================================
struct SmemT {
    float sin_[64][65];
    float sW[64*64];
};

__device__ __forceinline__ void kT_body(
    SmemT* sm, const float* __restrict__ feat, const float* __restrict__ Wg,
    float* __restrict__ outp, int p0, int HW)
{
    int tid = threadIdx.x;
    for (int i = tid; i < 4096; i += 256) sm->sW[i] = Wg[i];
    for (int e = tid; e < 4096; e += 256) {
        int c = e >> 6, p = e & 63;
        int gp = p0 + p;
        int b = gp / HW, hw = gp - b * HW;
        sm->sin_[p][c] = feat[(size_t)(b * 64 + c) * HW + hw];
    }
    __syncthreads();

    int cgrp = tid & 15, pgrp = tid >> 4;
    float acc[4][4];
#pragma unroll
    for (int i = 0; i < 4; i++)
#pragma unroll
        for (int j = 0; j < 4; j++) acc[i][j] = 0.f;

#pragma unroll 8
    for (int c = 0; c < 64; c++) {
        float4 w4 = *(const float4*)&sm->sW[c * 64 + cgrp * 4];
#pragma unroll
        for (int pp = 0; pp < 4; pp++) {
            float sv = sm->sin_[pgrp * 4 + pp][c];
            acc[pp][0] = fmaf(sv, w4.x, acc[pp][0]);
            acc[pp][1] = fmaf(sv, w4.y, acc[pp][1]);
            acc[pp][2] = fmaf(sv, w4.z, acc[pp][2]);
            acc[pp][3] = fmaf(sv, w4.w, acc[pp][3]);
        }
    }
#pragma unroll
    for (int pp = 0; pp < 4; pp++) {
        float4 r = make_float4(acc[pp][0], acc[pp][1], acc[pp][2], acc[pp][3]);
        *(float4*)&outp[(size_t)(p0 + pgrp * 4 + pp) * 64 + cgrp * 4] = r;
    }
}

// ===========================================================================
// kS body: sample + gate + relu + pair-max + group mean -> d_g[stage]
// 2 rows per 256-thread block.
// ===========================================================================
struct SmemS {
    int   sidx[2][72][4];
    float swt[2][72][4];
    float sgate[72];
    float sacc[2][4][64];
};

__device__ __forceinline__ void kS_body(
    SmemS* sm, int stage, int row0, int H, int W,
    const float* __restrict__ prior0, const float* __restrict__ l_weight)
{
    int tid = threadIdx.x;
    int htid = tid & 127, half = tid >> 7;
    int row = row0 + half;
    int b = row / 192, n = row - b * 192;

    if (tid < 72) sm->sgate[tid] = sigm(l_weight[tid]);
    if (htid < 72) {
        int o = htid;
        float px = (stage == 0) ? prior0[n * 72 + o] : d_prior[row * 72 + o];
        float gx = px * 2.0f - 1.0f;
        float ix = (gx + 1.0f) * 0.5f * (float)(W - 1);
        float yo = 1.0f - (float)o * (1.0f / 71.0f);
        float gy = yo * 2.0f - 1.0f;
        float iy = (gy + 1.0f) * 0.5f * (float)(H - 1);
        float ix0f = floorf(ix), iy0f = floorf(iy);
        float wx = ix - ix0f, wy = iy - iy0f;
        int ix0 = min(max((int)ix0f, 0), W - 1);
        int iy0 = min(max((int)iy0f, 0), H - 1);
        int ix1 = min(ix0 + 1, W - 1);
        int iy1 = min(iy0 + 1, H - 1);
        sm->sidx[half][o][0] = (iy0 * W + ix0) * 64;
        sm->sidx[half][o][1] = (iy0 * W + ix1) * 64;
        sm->sidx[half][o][2] = (iy1 * W + ix0) * 64;
        sm->sidx[half][o][3] = (iy1 * W + ix1) * 64;
        sm->swt[half][o][0] = (1.f - wx) * (1.f - wy);
        sm->swt[half][o][1] = wx * (1.f - wy);
        sm->swt[half][o][2] = (1.f - wx) * wy;
        sm->swt[half][o][3] = wx * wy;
    }
    __syncthreads();

    const float* Ft = (stage == 0) ? d_Ft0 : (stage == 1 ? d_Ft1 : d_Ft2);
    const float* base = Ft + (size_t)b * ((size_t)H * W * 64);
    int c4 = htid & 15, osub = htid >> 4;

    float4 acc = make_float4(0.f, 0.f, 0.f, 0.f);
#pragma unroll
    for (int it = 0; it < 9; it++) {
        int o = it * 8 + osub;
        const int* si = sm->sidx[half][o];
        float4 a0 = *((const float4*)(base + si[0]) + c4);
        float4 a1 = *((const float4*)(base + si[1]) + c4);
        float4 a2 = *((const float4*)(base + si[2]) + c4);
        float4 a3 = *((const float4*)(base + si[3]) + c4);
        float w0 = sm->swt[half][o][0], w1 = sm->swt[half][o][1];
        float w2 = sm->swt[half][o][2], w3 = sm->swt[half][o][3];
        float g = sm->sgate[o];
        float4 r;
        r.x = fmaxf(0.f, g * (w0 * a0.x + w1 * a1.x + w2 * a2.x + w3 * a3.x));
        r.y = fmaxf(0.f, g * (w0 * a0.y + w1 * a1.y + w2 * a2.y + w3 * a3.y));
        r.z = fmaxf(0.f, g * (w0 * a0.z + w1 * a1.z + w2 * a2.z + w3 * a3.z));
        r.w = fmaxf(0.f, g * (w0 * a0.w + w1 * a1.w + w2 * a2.w + w3 * a3.w));
        float qx = __shfl_xor_sync(0xffffffffu, r.x, 16);
        float qy = __shfl_xor_sync(0xffffffffu, r.y, 16);
        float qz = __shfl_xor_sync(0xffffffffu, r.z, 16);
        float qw = __shfl_xor_sync(0xffffffffu, r.w, 16);
        if ((osub & 1) == 0) {
            acc.x += fmaxf(r.x, qx);
            acc.y += fmaxf(r.y, qy);
            acc.z += fmaxf(r.z, qz);
            acc.w += fmaxf(r.w, qw);
        }
    }
    if ((osub & 1) == 0) {
        int w = (htid >> 5) & 3;
        *(float4*)&sm->sacc[half][w][c4 * 4] = acc;
    }
    __syncthreads();

    if (htid < 64) {
        int u = htid;
        float fv = sm->sacc[half][0][u] + sm->sacc[half][1][u] +
                   sm->sacc[half][2][u] + sm->sacc[half][3][u];
        d_g[stage][(size_t)row * 64 + u] = fv * (1.0f / 36.0f);
    }
}

// ===========================================================================
// kH: weight-stationary GEMM heads. 32 rows/block, 256 threads, grid = 192.
// ===========================================================================
struct SmemH {
    float A[32][65];
    float Bf[32][65];
    float D[32][65];
    float W[64*64];
};

__device__ __forceinline__ void gemm64(
    SmemH* sm, const float (*In)[65], float (*Out)[65],
    const float* __restrict__ Wg, const float* __restrict__ bg, int tid)
{
    for (int i = tid; i < 4096; i += 256) sm->W[i] = Wg[i];
    __syncthreads();
    int u0 = (tid & 15) * 4, r0 = (tid >> 4) * 2;
    float b0 = bg[u0], b1 = bg[u0 + 1], b2 = bg[u0 + 2], b3 = bg[u0 + 3];
    float acc[2][4] = {{b0, b1, b2, b3}, {b0, b1, b2, b3}};
#pragma unroll 8
    for (int k = 0; k < 64; k++) {
        float4 w4 = *(const float4*)&sm->W[k * 64 + u0];
        float a0 = In[r0][k], a1 = In[r0 + 1][k];
        acc[0][0] = fmaf(a0, w4.x, acc[0][0]);
        acc[0][1] = fmaf(a0, w4.y, acc[0][1]);
        acc[0][2] = fmaf(a0, w4.z, acc[0][2]);
        acc[0][3] = fmaf(a0, w4.w, acc[0][3]);
        acc[1][0] = fmaf(a1, w4.x, acc[1][0]);
        acc[1][1] = fmaf(a1, w4.y, acc[1][1]);
        acc[1][2] = fmaf(a1, w4.z, acc[1][2]);
        acc[1][3] = fmaf(a1, w4.w, acc[1][3]);
    }
#pragma unroll
    for (int r = 0; r < 2; r++)
#pragma unroll
        for (int j = 0; j < 4; j++)
            Out[r0 + r][u0 + j] = fmaxf(acc[r][j], 0.f);
    __syncthreads();
}

__global__ __launch_bounds__(256, 2)
void kH(int s,
        const float* __restrict__ fc_w,  const float* __restrict__ fc_b,
        const float* __restrict__ cls_w, const float* __restrict__ cls_b,
        const float* __restrict__ cls_ow,const float* __restrict__ cls_ob,
        const float* __restrict__ reg_w, const float* __restrict__ reg_b,
        const float* __restrict__ reg_ow,const float* __restrict__ reg_ob,
        const float* __restrict__ loc_w, const float* __restrict__ loc_b,
        const float* __restrict__ loc_ow,const float* __restrict__ loc_ob,
        float* __restrict__ out)
{
    __shared__ SmemH sm;
    int tid = threadIdx.x;
    int row0 = blockIdx.x * 32;
    float inv = 1.0f / (float)(s + 1);

    for (int e = tid; e < 2048; e += 256) {
        int r = e >> 6, u = e & 63;
        size_t off = (size_t)(row0 + r) * 64 + u;
        float fv = d_g[0][off];
        if (s >= 1) fv += d_g[1][off];
        if (s >= 2) fv += d_g[2][off];
        sm.A[r][u] = fv * inv;
    }
    __syncthreads();

    gemm64(&sm, sm.A, sm.Bf, fc_w, fc_b, tid);                 // Bf = relu(fc)

    // ---- cls ----
    gemm64(&sm, sm.Bf, sm.A, cls_w, cls_b, tid);
    gemm64(&sm, sm.A, sm.D, cls_w + 4096, cls_b + 64, tid);
    for (int e = tid; e < 64; e += 256) {
        int r = e >> 1, u = e & 1;
        float a = cls_ob[u];
#pragma unroll
        for (int i = 0; i < 64; i++) a = fmaf(sm.D[r][i], cls_ow[i * 2 + u], a);
        out[((size_t)s * ROWS + row0 + r) * 79 + u] = a;
    }

    // ---- reg ---- (gemm64's internal sync orders against clsout)
    gemm64(&sm, sm.Bf, sm.A, reg_w, reg_b, tid);
    gemm64(&sm, sm.A, sm.D, reg_w + 4096, reg_b + 64, tid);
    for (int e = tid; e < 32 * 76; e += 256) {
        int r = e / 76, u = e - r * 76;
        float a = reg_ob[u];
#pragma unroll
        for (int i = 0; i < 64; i++) a = fmaf(sm.D[r][i], reg_ow[i * 76 + u], a);
        int row = row0 + r;
        out[((size_t)s * ROWS + row) * 79 + 2 + u] = a;
        if (u >= 4) d_prior[(size_t)row * 72 + (u - 4)] = sigm(a);
    }

    // ---- loc ----
    gemm64(&sm, sm.Bf, sm.A, loc_w, loc_b, tid);
    gemm64(&sm, sm.A, sm.D, loc_w + 4096, loc_b + 64, tid);
    if (tid < 32) {
        float a = loc_ob[0];
#pragma unroll
        for (int i = 0; i < 64; i++) a = fmaf(sm.D[tid][i], loc_ow[i], a);
        out[((size_t)s * ROWS + row0 + tid) * 79 + 78] = a;
    }
}

// ===========================================================================
// Kernels
// ===========================================================================
__global__ __launch_bounds__(256)
void kT0(const float* __restrict__ x2, const float* __restrict__ lsgi_w) {
    __shared__ SmemT sm;
    kT_body(&sm, x2, lsgi_w, d_Ft0, blockIdx.x * 64, 250);
}

// Mixed launch: interleaved kS(stage0) blocks (3072) + kT(stage1/2) blocks (2500)
__global__ __launch_bounds__(256)
void kMix(const float* __restrict__ x0, const float* __restrict__ x1,
          const float* __restrict__ lsgi_w,
          const float* __restrict__ prior0, const float* __restrict__ l_weight)
{
    __shared__ union USm { SmemT t; SmemS s; } sm;
    int bx = blockIdx.x;
    bool isT; int idx;
    if (bx < 5000) { isT = ((bx & 1) == 0); idx = bx >> 1; }
    else           { isT = false; idx = 2500 + (bx - 5000); }

    if (isT) {
        if (idx < 500) kT_body(&sm.t, x1, lsgi_w + 4096, d_Ft1, idx * 64, 1000);
        else           kT_body(&sm.t, x0, lsgi_w + 8192, d_Ft2, (idx - 500) * 64, 4000);
    } else {
        kS_body(&sm.s, 0, idx * 2, 10, 25, prior0, l_weight);
    }
}

__global__ __launch_bounds__(256)
void kSk(int stage, int H, int W,
         const float* __restrict__ prior0, const float* __restrict__ l_weight)
{
    __shared__ SmemS sm;
    kS_body(&sm, stage, blockIdx.x * 2, H, W, prior0, l_weight);
}

// ===========================================================================
extern "C" void kernel_launch(void* const* d_in, const int* in_sizes, int n_in,
                              void* d_out, int out_size) {
    const float* x0       = (const float*)d_in[0];
    const float* x1       = (const float*)d_in[1];
    const float* x2       = (const float*)d_in[2];
    const float* prior0   = (const float*)d_in[3];
    const float* l_weight = (const float*)d_in[4];
    const float* lsgi_w   = (const float*)d_in[5];
    const float* fc_w     = (const float*)d_in[6];
    const float* fc_b     = (const float*)d_in[7];
    const float* cls_w    = (const float*)d_in[8];
    const float* cls_b    = (const float*)d_in[9];
    const float* cls_ow   = (const float*)d_in[10];
    const float* cls_ob   = (const float*)d_in[11];
    const float* reg_w    = (const float*)d_in[12];
    const float* reg_b    = (const float*)d_in[13];
    const float* reg_ow   = (const float*)d_in[14];
    const float* reg_ob   = (const float*)d_in[15];
    const float* loc_w    = (const float*)d_in[16];
    const float* loc_b    = (const float*)d_in[17];
    const float* loc_ow   = (const float*)d_in[18];
    const float* loc_ob   = (const float*)d_in[19];
    float* out = (float*)d_out;

    kT0<<<125, 256>>>(x2, lsgi_w);
    kMix<<<5572, 256>>>(x0, x1, lsgi_w, prior0, l_weight);
    kH<<<192, 256>>>(0, fc_w, fc_b, cls_w, cls_b, cls_ow, cls_ob,
                     reg_w, reg_b, reg_ow, reg_ob, loc_w, loc_b, loc_ow, loc_ob, out);

    kSk<<<3072, 256>>>(1, 20, 50, prior0, l_weight);
    kH<<<192, 256>>>(1, fc_w, fc_b, cls_w, cls_b, cls_ow, cls_ob,
                     reg_w, reg_b, reg_ow, reg_ob, loc_w, loc_b, loc_ow, loc_ob, out);

    kSk<<<3072, 256>>>(2, 40, 100, prior0, l_weight);
    kH<<<192, 256>>>(2, fc_w, fc_b, cls_w, cls_b, cls_ow, cls_ob,
                     reg_w, reg_b, reg_ow, reg_ob, loc_w, loc_b, loc_ow, loc_ob, out);
}